// round 15
// baseline (speedup 1.0000x reference)
#include <cuda_runtime.h>
#include <cuda_bf16.h>
#include <cuda_fp16.h>
#include <math.h>
#include <float.h>
#include <stdint.h>

// ---------------------------------------------------------------------------
// MultiLabelGCN on GB300 — fp16 m16n8k16, 512-thread CTAs, 2 CTAs/SM
// (32 warps/SM). M=66, N=256 per CTA; acc 48 regs/thread; B fragments via
// cp.async smem double-buffer (frees registers); fp32 activations.
// ---------------------------------------------------------------------------

#define NUM_JOINTS 33
#define BATCH      4096
#define NN_ROWS    (BATCH * NUM_JOINTS)   // 135168
#define HDIM       256
#define NN_INV     (1.0f / 135168.0f)

#define NTILES (NN_ROWS / 66)       // 2048 CTAs
#define TROWS  66

// smem layout (bytes)
#define OFF_IN     0                        // float [3][66][36]   28512
#define INBUF      9504
#define OFF_A2     28512                    // u32 [2][1280]       10240
#define OFF_B      38752                    // u8  [2][16384]      32768
#define OFF_SCALE  71520                    // float [256]          1024
#define OFF_SHIFT  72544                    // float [256]          1024
#define OFF_STAT   73568                    // float [512]          2048
#define OFF_NW     75616                    // float [103] + pad     512
#define SMEM_BYTES 76160

__constant__ int ADJ_OFF[34] = {
    0,3,6,9,12,15,18,21,23,25,27,29,33,37,40,43,48,53,56,59,62,65,
    67,69,73,77,80,83,87,91,94,97,100,103};
__constant__ int ADJ_NB[103] = {
    1,4,0,  0,2,1,  1,3,2,  2,7,3,  0,5,4,  4,6,5,  5,8,6,  3,7,  6,8,
    10,9,  9,10,  12,13,23,11,  11,14,24,12,  11,15,13,  12,16,14,
    13,17,19,21,15,  14,18,20,22,16,  15,19,17,  16,20,18,  15,17,19,
    16,18,20,  15,21,  16,22,  11,24,25,23,  12,23,26,24,  23,27,25,
    24,28,26,  25,29,31,27,  26,30,32,28,  27,31,29,  28,32,30,
    29,27,31,  30,28,32};
__constant__ float DEGF[33] = {
    3,3,3,3,3,3,3,2,2,2,2,4,4,3,3,5,5,3,3,3,3,2,2,4,4,3,3,4,4,3,3,3,3};

// scratch — fp32 activations
__device__ float g_bufA[(size_t)NN_ROWS * HDIM];
__device__ float g_bufB[(size_t)NN_ROWS * HDIM];
__device__ float g_stats[3 * 512];
__device__ uint2 g_wpackH[4 * 8 * 32 * 2 * 32];  // [mat][chunk][ntile][s][lane]

// ---------------------------------------------------------------------------
__device__ __forceinline__ uint32_t pack_h2(float a, float b) {
    __half2 h = __float22half2_rn(make_float2(a, b));
    return *(uint32_t*)&h;
}
__device__ __forceinline__ void mma_f16(float* d, const uint32_t* a, const uint32_t* b) {
    asm volatile(
        "mma.sync.aligned.m16n8k16.row.col.f32.f16.f16.f32 "
        "{%0,%1,%2,%3}, {%4,%5,%6,%7}, {%8,%9}, {%0,%1,%2,%3};\n"
        : "+f"(d[0]), "+f"(d[1]), "+f"(d[2]), "+f"(d[3])
        : "r"(a[0]), "r"(a[1]), "r"(a[2]), "r"(a[3]), "r"(b[0]), "r"(b[1]));
}
__device__ __forceinline__ void cp16(void* dst, const void* src) {
    uint32_t d = (uint32_t)__cvta_generic_to_shared(dst);
    asm volatile("cp.async.cg.shared.global [%0], [%1], 16;\n" :: "r"(d), "l"(src));
}
#define CP_COMMIT() asm volatile("cp.async.commit_group;\n")
#define CP_WAIT2()  asm volatile("cp.async.wait_group 2;\n")
#define CP_WAIT3()  asm volatile("cp.async.wait_group 3;\n")

__device__ __forceinline__ float fixv(float f) {
    if (isnan(f)) return 0.0f;
    if (isinf(f)) return (f > 0.0f) ? FLT_MAX : -FLT_MAX;
    return f;
}

// ---------------------------------------------------------------------------
// pack weights -> fp16 B fragments (layout verified R10-R14)
// ---------------------------------------------------------------------------
__global__ void pack_w(const float* __restrict__ w0, const float* __restrict__ w1,
                       const float* __restrict__ w2, const float* __restrict__ wh)
{
    int idx = blockIdx.x * blockDim.x + threadIdx.x;   // 0..65535
    int lane  = idx & 31;
    int s     = (idx >> 5) & 1;
    int ntile = (idx >> 6) & 31;
    int c     = (idx >> 11) & 7;
    int m     = idx >> 14;
    const float* W = (m == 0) ? w0 : (m == 1) ? w1 : (m == 2) ? w2 : wh;
    int k0 = c * 32 + s * 16;
    int n  = ntile * 8 + (lane >> 2);
    int t  = lane & 3;
    uint2 v;
    v.x = pack_h2(W[(size_t)(k0 + 2*t)     * HDIM + n], W[(size_t)(k0 + 2*t + 1) * HDIM + n]);
    v.y = pack_h2(W[(size_t)(k0 + 2*t + 8) * HDIM + n], W[(size_t)(k0 + 2*t + 9) * HDIM + n]);
    g_wpackH[idx] = v;
}

__global__ void zero_stats_kernel(float* stats) {
    int i = blockIdx.x * blockDim.x + threadIdx.x;
    if (i < 3 * 512) stats[i] = 0.0f;
}

// ---------------------------------------------------------------------------
// fused layer. grid = NTILES (2048), block = 512, 2 CTAs/SM (32 warps).
// ---------------------------------------------------------------------------
__global__ void __launch_bounds__(512, 2)
fused_layer(const float* __restrict__ in, int wsel, const float* __restrict__ bias,
            float* __restrict__ out, const float* __restrict__ stats_in,
            const float* __restrict__ gam, const float* __restrict__ bet,
            float* __restrict__ stats_out, int mode)
{
    extern __shared__ char smem[];
    float*    sIn   = (float*)(smem + OFF_IN);     // [3][66][36]
    uint32_t* sA2   = (uint32_t*)(smem + OFF_A2);  // [2][1280]
    char*     sB    = (char*)(smem + OFF_B);       // [2][16384]
    float*    sScale= (float*)(smem + OFF_SCALE);
    float*    sShift= (float*)(smem + OFF_SHIFT);
    float*    sStat = (float*)(smem + OFF_STAT);
    float*    sNW   = (float*)(smem + OFF_NW);

    const int tid = threadIdx.x, lane = tid & 31, warp = tid >> 5;   // 16 warps
    const int wm = warp >> 3, wn = warp & 7;
    const int p = blockIdx.x;
    const int rowBase = p * TROWS;
    const float* src = in + (size_t)rowBase * HDIM;
    const char* wbase = (const char*)(g_wpackH + (size_t)wsel * (8 * 32 * 2 * 32));

    // ---- init ----
    if (tid < NUM_JOINTS) {
        float dn = rsqrtf(DEGF[tid]);
        for (int e = ADJ_OFF[tid]; e < ADJ_OFF[tid + 1]; e++)
            sNW[e] = dn * rsqrtf(DEGF[ADJ_NB[e]]);
    }
    if (tid < 256) {
        if (mode == 1) {
            float mu  = stats_in[tid] * NN_INV;
            float ex2 = stats_in[256 + tid] * NN_INV;
            float inv = rsqrtf(ex2 - mu * mu + 1e-5f);
            float sc  = inv * gam[tid];
            sScale[tid] = sc;
            sShift[tid] = bet[tid] - mu * sc;
        } else {
            sScale[tid] = 1.0f;
            sShift[tid] = 0.0f;
        }
    }
    sStat[tid] = 0.0f;
    // zero both A-fragment buffers (pad rows stay zero forever)
    for (int i = tid; i < 2560; i += 512) sA2[i] = 0;

    // ---- prologue commits: in[0] | W[0] | in[1]  (3 groups) ----
    for (int j = tid; j < 528; j += 512) {
        int r = j >> 3, seg = j & 7;
        cp16((char*)sIn + r * 144 + seg * 16, src + (size_t)r * HDIM + seg * 4);
    }
    CP_COMMIT();
    for (int j = tid; j < 1024; j += 512)
        cp16(sB + j * 16, wbase + j * 16);
    CP_COMMIT();
    for (int j = tid; j < 528; j += 512) {
        int r = j >> 3, seg = j & 7;
        cp16((char*)sIn + INBUF + r * 144 + seg * 16,
             src + (size_t)r * HDIM + 32 + seg * 4);
    }
    CP_COMMIT();

    float acc[3][4][4];
    #pragma unroll
    for (int i = 0; i < 3; i++)
        #pragma unroll
        for (int nt = 0; nt < 4; nt++)
            #pragma unroll
            for (int j = 0; j < 4; j++) acc[i][nt][j] = 0.0f;

    const int pair  = lane & 15;
    const int rbase = warp + 16 * (lane >> 4);   // 0..31

    for (int c = 0; c < 8; c++) {
        CP_WAIT2();
        __syncthreads();   // bar1: in[c] visible; MMA[c-1]/agg[c-1] retired

        // ---- stage W[c+1] into sB[(c+1)&1] (last read by MMA[c-1]) ----
        if (c + 1 < 8) {
            char* dB = sB + ((c + 1) & 1) * 16384;
            const char* sW = wbase + (c + 1) * 16384;
            for (int j = tid; j < 1024; j += 512)
                cp16(dB + j * 16, sW + j * 16);
        }
        CP_COMMIT();

        // ---- transform in[c] IN PLACE: BN+ReLU / nan_to_num ----
        {
            float* sInc = sIn + (c % 3) * (66 * 36);
            const int cb = c * 32;
            for (int j = tid; j < 1056; j += 512) {
                int r = j >> 4, pr = j & 15;
                float2* a = (float2*)&sInc[r * 36 + pr * 2];
                float2 f = *a;
                if (mode == 0) {
                    f.x = fixv(f.x); f.y = fixv(f.y);
                } else {
                    float2 sc = *(const float2*)&sScale[cb + pr * 2];
                    float2 sh = *(const float2*)&sShift[cb + pr * 2];
                    f.x = fmaxf(fmaf(f.x, sc.x, sh.x), 0.0f);
                    f.y = fmaxf(fmaf(f.y, sc.y, sh.y), 0.0f);
                }
                *a = f;
            }
        }

        // ---- stage in[c+2] ----
        if (c + 2 < 8) {
            char* dI = (char*)sIn + ((c + 2) % 3) * INBUF;
            const float* sN = src + (c + 2) * 32;
            for (int j = tid; j < 528; j += 512) {
                int r = j >> 3, seg = j & 7;
                cp16(dI + r * 144 + seg * 16, sN + (size_t)r * HDIM + seg * 4);
            }
        }
        CP_COMMIT();

        __syncthreads();   // bar2: transformed in[c] visible

        // ---- agg[c]: pure stencil -> fp16 fragments in sA2[c&1] ----
        {
            const float* sInc = sIn + (c % 3) * (66 * 36);
            uint32_t* sAc = sA2 + (c & 1) * 1280;
            #pragma unroll
            for (int j = 0; j < 3; j++) {
                int r = rbase + 32 * j;
                if (r < TROWS) {
                    int n  = (r >= NUM_JOINTS) ? r - NUM_JOINTS : r;
                    int lb = (r >= NUM_JOINTS) ? NUM_JOINTS : 0;
                    float ax = 0.0f, ay = 0.0f;
                    int e1 = ADJ_OFF[n + 1];
                    for (int e = ADJ_OFF[n]; e < e1; e++) {
                        float2 f = *(const float2*)&sInc[(lb + ADJ_NB[e]) * 36 + pair * 2];
                        float w = sNW[e];
                        ax = fmaf(w, f.x, ax);
                        ay = fmaf(w, f.y, ay);
                    }
                    int tl   = r >> 4;
                    int s    = pair >> 3;
                    int lp   = (r & 7) * 4 + (pair & 3);
                    int comp = ((r >> 3) & 1) + (((pair >> 2) & 1) << 1);
                    sAc[((tl * 2 + s) * 32 + lp) * 4 + comp] = pack_h2(ax, ay);
                }
            }
        }

        CP_WAIT3();        // W[c] complete (this thread)
        __syncthreads();   // bar3: sA2[c&1] + W[c] visible to all

        // ---- MMA[c]: A LDS.128 + B LDS.64 from smem ----
        {
            const uint32_t* sAc = sA2 + (c & 1) * 1280;
            const char* sBc = sB + (c & 1) * 16384;
            #pragma unroll
            for (int s = 0; s < 2; s++) {
                uint2 bfr[4];
                #pragma unroll
                for (int nt = 0; nt < 4; nt++)
                    bfr[nt] = *(const uint2*)(sBc + (((wn * 4 + nt) * 2 + s) * 32 + lane) * 8);
                #pragma unroll
                for (int tl = 0; tl < 3; tl++) {
                    int tlg = wm * 3 + tl;
                    if (tlg < 5) {
                        uint4 av = *(const uint4*)&sAc[((tlg * 2 + s) * 32 + lane) * 4];
                        const uint32_t* af = (const uint32_t*)&av;
                        #pragma unroll
                        for (int nt = 0; nt < 4; nt++)
                            mma_f16(acc[tl][nt], af, (const uint32_t*)&bfr[nt]);
                    }
                }
            }
        }
    }

    // ---- epilogue: bias, store, stats (warp: rows wm-half, cols wn*32..) ----
    float bval[8];
    #pragma unroll
    for (int nt = 0; nt < 4; nt++) {
        int col = wn * 32 + nt * 8 + 2 * (lane & 3);
        bval[nt * 2 + 0] = bias[col];
        bval[nt * 2 + 1] = bias[col + 1];
    }
    float cs1[8], cs2[8];
    #pragma unroll
    for (int j = 0; j < 8; j++) { cs1[j] = 0.0f; cs2[j] = 0.0f; }

    #pragma unroll
    for (int tl = 0; tl < 3; tl++) {
        int tlg = wm * 3 + tl;
        if (tlg < 5) {
            int rb = tlg * 16 + (lane >> 2);
            #pragma unroll
            for (int nt = 0; nt < 4; nt++) {
                int col = wn * 32 + nt * 8 + 2 * (lane & 3);
                if (rb < TROWS) {
                    float z0 = acc[tl][nt][0] + bval[nt * 2 + 0];
                    float z1 = acc[tl][nt][1] + bval[nt * 2 + 1];
                    *(float2*)(out + (size_t)(rowBase + rb) * HDIM + col) = make_float2(z0, z1);
                    cs1[nt * 2 + 0] += z0; cs2[nt * 2 + 0] = fmaf(z0, z0, cs2[nt * 2 + 0]);
                    cs1[nt * 2 + 1] += z1; cs2[nt * 2 + 1] = fmaf(z1, z1, cs2[nt * 2 + 1]);
                }
                int r2 = rb + 8;
                if (r2 < TROWS) {
                    float z2 = acc[tl][nt][2] + bval[nt * 2 + 0];
                    float z3 = acc[tl][nt][3] + bval[nt * 2 + 1];
                    *(float2*)(out + (size_t)(rowBase + r2) * HDIM + col) = make_float2(z2, z3);
                    cs1[nt * 2 + 0] += z2; cs2[nt * 2 + 0] = fmaf(z2, z2, cs2[nt * 2 + 0]);
                    cs1[nt * 2 + 1] += z3; cs2[nt * 2 + 1] = fmaf(z3, z3, cs2[nt * 2 + 1]);
                }
            }
        }
    }

    if (stats_out != nullptr) {
        #pragma unroll
        for (int j = 0; j < 8; j++) {
            int cl = wn * 32 + (j >> 1) * 8 + 2 * (lane & 3) + (j & 1);
            atomicAdd(&sStat[cl], cs1[j]);
            atomicAdd(&sStat[256 + cl], cs2[j]);
        }
        __syncthreads();
        if (tid < 256) {
            atomicAdd(&stats_out[tid], sStat[tid]);
            atomicAdd(&stats_out[256 + tid], sStat[256 + tid]);
        }
    }
}

// ---------------------------------------------------------------------------
__global__ void __launch_bounds__(256)
pool_kernel(const float* __restrict__ h, const float* __restrict__ wc,
            const float* __restrict__ bc, float* __restrict__ out)
{
    const int g = blockIdx.x;
    const int tid = threadIdx.x;
    const int lane = tid & 31, warp = tid >> 5;
    const size_t base = (size_t)g * NUM_JOINTS * HDIM;

    float s = 0.0f;
    #pragma unroll
    for (int n = 0; n < NUM_JOINTS; n++) s += h[base + n * HDIM + tid];
    s *= (1.0f / 33.0f);

    float4 wv = *(const float4*)(wc + tid * 4);
    float p0 = s * wv.x, p1 = s * wv.y, p2 = s * wv.z, p3 = s * wv.w;
    #pragma unroll
    for (int off = 16; off > 0; off >>= 1) {
        p0 += __shfl_down_sync(0xFFFFFFFF, p0, off);
        p1 += __shfl_down_sync(0xFFFFFFFF, p1, off);
        p2 += __shfl_down_sync(0xFFFFFFFF, p2, off);
        p3 += __shfl_down_sync(0xFFFFFFFF, p3, off);
    }
    __shared__ float4 part[8];
    if (lane == 0) part[warp] = make_float4(p0, p1, p2, p3);
    __syncthreads();
    if (tid == 0) {
        float4 o = make_float4(bc[0], bc[1], bc[2], bc[3]);
        #pragma unroll
        for (int w = 0; w < 8; w++) {
            o.x += part[w].x; o.y += part[w].y; o.z += part[w].z; o.w += part[w].w;
        }
        *(float4*)(out + g * 4) = o;
    }
}

// ---------------------------------------------------------------------------
extern "C" void kernel_launch(void* const* d_in, const int* in_sizes, int n_in,
                              void* d_out, int out_size)
{
    const float* x   = (const float*)d_in[0];
    const float* w0  = (const float*)d_in[1];
    const float* b0  = (const float*)d_in[2];
    const float* g0  = (const float*)d_in[3];
    const float* be0 = (const float*)d_in[4];
    const float* w1  = (const float*)d_in[5];
    const float* b1  = (const float*)d_in[6];
    const float* g1  = (const float*)d_in[7];
    const float* be1 = (const float*)d_in[8];
    const float* w2  = (const float*)d_in[9];
    const float* b2  = (const float*)d_in[10];
    const float* g2  = (const float*)d_in[11];
    const float* be2 = (const float*)d_in[12];
    const float* wh  = (const float*)d_in[13];
    const float* bh  = (const float*)d_in[14];
    const float* wc  = (const float*)d_in[15];
    const float* bc  = (const float*)d_in[16];

    float *bufA, *bufB, *stats;
    cudaGetSymbolAddress((void**)&bufA, g_bufA);
    cudaGetSymbolAddress((void**)&bufB, g_bufB);
    cudaGetSymbolAddress((void**)&stats, g_stats);

    cudaFuncSetAttribute(fused_layer, cudaFuncAttributeMaxDynamicSharedMemorySize,
                         SMEM_BYTES);

    pack_w<<<256, 256>>>(w0, w1, w2, wh);
    zero_stats_kernel<<<6, 256>>>(stats);

    fused_layer<<<NTILES, 512, SMEM_BYTES>>>(x,    0, b0, bufB, nullptr, nullptr, nullptr, stats, 0);
    fused_layer<<<NTILES, 512, SMEM_BYTES>>>(bufB, 1, b1, bufA, stats,        g0, be0, stats + 512, 1);
    fused_layer<<<NTILES, 512, SMEM_BYTES>>>(bufA, 2, b2, bufB, stats + 512,  g1, be1, stats + 1024, 1);
    fused_layer<<<NTILES, 512, SMEM_BYTES>>>(bufB, 3, bh, bufA, stats + 1024, g2, be2, nullptr, 1);
    pool_kernel<<<BATCH, 256>>>(bufA, wc, bc, (float*)d_out);
}

// round 16
// speedup vs baseline: 1.1878x; 1.1878x over previous
#include <cuda_runtime.h>
#include <cuda_bf16.h>
#include <cuda_fp16.h>
#include <math.h>
#include <float.h>
#include <stdint.h>

// ---------------------------------------------------------------------------
// MultiLabelGCN on GB300 — R16: stencil moved to the epilogue.
//   Z = (BN_ReLU(H)) @ W   via fp16 m16n8k16, input LDG'd straight into
//   fragments (1 barrier/chunk, no staging);  U = A_hat * Z + b  applied once
//   per layer in a per-warp smem slab epilogue. 2 CTAs/SM.
// ---------------------------------------------------------------------------

#define NUM_JOINTS 33
#define BATCH      4096
#define NN_ROWS    (BATCH * NUM_JOINTS)   // 135168
#define HDIM       256
#define NN_INV     (1.0f / 135168.0f)

#define NTILES (NN_ROWS / 66)       // 2048 CTAs
#define TROWS  66

// smem layout (bytes)
#define OFF_A2     0                        // u32 [2][1280]       10240
#define OFF_SLAB   10240                    // float [8][80*16]    40960
#define OFF_SCALE  51200                    // float [256]          1024
#define OFF_SHIFT  52224                    // float [256]          1024
#define OFF_STAT   53248                    // float [512]          2048
#define OFF_NW     55296                    // float [103] + pad     512
#define SMEM_BYTES 55808

__constant__ int ADJ_OFF[34] = {
    0,3,6,9,12,15,18,21,23,25,27,29,33,37,40,43,48,53,56,59,62,65,
    67,69,73,77,80,83,87,91,94,97,100,103};
__constant__ int ADJ_NB[103] = {
    1,4,0,  0,2,1,  1,3,2,  2,7,3,  0,5,4,  4,6,5,  5,8,6,  3,7,  6,8,
    10,9,  9,10,  12,13,23,11,  11,14,24,12,  11,15,13,  12,16,14,
    13,17,19,21,15,  14,18,20,22,16,  15,19,17,  16,20,18,  15,17,19,
    16,18,20,  15,21,  16,22,  11,24,25,23,  12,23,26,24,  23,27,25,
    24,28,26,  25,29,31,27,  26,30,32,28,  27,31,29,  28,32,30,
    29,27,31,  30,28,32};
__constant__ float DEGF[33] = {
    3,3,3,3,3,3,3,2,2,2,2,4,4,3,3,5,5,3,3,3,3,2,2,4,4,3,3,4,4,3,3,3,3};

// scratch — fp32 activations
__device__ float g_bufA[(size_t)NN_ROWS * HDIM];
__device__ float g_bufB[(size_t)NN_ROWS * HDIM];
__device__ float g_stats[3 * 512];
__device__ uint2 g_wpackH[4 * 8 * 32 * 2 * 32];  // [mat][chunk][ntile][s][lane]

// ---------------------------------------------------------------------------
__device__ __forceinline__ uint32_t pack_h2(float a, float b) {
    __half2 h = __float22half2_rn(make_float2(a, b));
    return *(uint32_t*)&h;
}
__device__ __forceinline__ void mma_f16(float* d, const uint32_t* a, const uint32_t* b) {
    asm volatile(
        "mma.sync.aligned.m16n8k16.row.col.f32.f16.f16.f32 "
        "{%0,%1,%2,%3}, {%4,%5,%6,%7}, {%8,%9}, {%0,%1,%2,%3};\n"
        : "+f"(d[0]), "+f"(d[1]), "+f"(d[2]), "+f"(d[3])
        : "r"(a[0]), "r"(a[1]), "r"(a[2]), "r"(a[3]), "r"(b[0]), "r"(b[1]));
}
__device__ __forceinline__ float fixv(float f) {
    if (isnan(f)) return 0.0f;
    return fminf(fmaxf(f, -60000.0f), 60000.0f);
}

// ---------------------------------------------------------------------------
// pack weights -> fp16 B fragments (layout verified R10-R15)
// ---------------------------------------------------------------------------
__global__ void pack_w(const float* __restrict__ w0, const float* __restrict__ w1,
                       const float* __restrict__ w2, const float* __restrict__ wh)
{
    int idx = blockIdx.x * blockDim.x + threadIdx.x;   // 0..65535
    int lane  = idx & 31;
    int s     = (idx >> 5) & 1;
    int ntile = (idx >> 6) & 31;
    int c     = (idx >> 11) & 7;
    int m     = idx >> 14;
    const float* W = (m == 0) ? w0 : (m == 1) ? w1 : (m == 2) ? w2 : wh;
    int k0 = c * 32 + s * 16;
    int n  = ntile * 8 + (lane >> 2);
    int t  = lane & 3;
    uint2 v;
    v.x = pack_h2(W[(size_t)(k0 + 2*t)     * HDIM + n], W[(size_t)(k0 + 2*t + 1) * HDIM + n]);
    v.y = pack_h2(W[(size_t)(k0 + 2*t + 8) * HDIM + n], W[(size_t)(k0 + 2*t + 9) * HDIM + n]);
    g_wpackH[idx] = v;
}

__global__ void zero_stats_kernel(float* stats) {
    int i = blockIdx.x * blockDim.x + threadIdx.x;
    if (i < 3 * 512) stats[i] = 0.0f;
}

// ---------------------------------------------------------------------------
// fused layer. grid = NTILES (2048), block = 256, 2 CTAs/SM.
// ---------------------------------------------------------------------------
__global__ void __launch_bounds__(256, 2)
fused_layer(const float* __restrict__ in, int wsel, const float* __restrict__ bias,
            float* __restrict__ out, const float* __restrict__ stats_in,
            const float* __restrict__ gam, const float* __restrict__ bet,
            float* __restrict__ stats_out, int mode)
{
    extern __shared__ char smem[];
    uint32_t* sA2   = (uint32_t*)(smem + OFF_A2);  // [2][1280]
    float*    sSlab = (float*)(smem + OFF_SLAB);   // [8][80*16]
    float*    sScale= (float*)(smem + OFF_SCALE);
    float*    sShift= (float*)(smem + OFF_SHIFT);
    float*    sStat = (float*)(smem + OFF_STAT);
    float*    sNW   = (float*)(smem + OFF_NW);

    const int tid = threadIdx.x, lane = tid & 31, warp = tid >> 5;   // 8 warps
    const int p = blockIdx.x;
    const int rowBase = p * TROWS;
    const float* src = in + (size_t)rowBase * HDIM;
    const uint2* wbase = g_wpackH + (size_t)wsel * (8 * 32 * 2 * 32);

    // ---- init ----
    if (tid < NUM_JOINTS) {
        float dn = rsqrtf(DEGF[tid]);
        for (int e = ADJ_OFF[tid]; e < ADJ_OFF[tid + 1]; e++)
            sNW[e] = dn * rsqrtf(DEGF[ADJ_NB[e]]);
    }
    if (mode == 1) {
        float mu  = stats_in[tid] * NN_INV;
        float ex2 = stats_in[256 + tid] * NN_INV;
        float inv = rsqrtf(ex2 - mu * mu + 1e-5f);
        float sc  = inv * gam[tid];
        sScale[tid] = sc;
        sShift[tid] = bet[tid] - mu * sc;
    } else {
        sScale[tid] = 1.0f;
        sShift[tid] = 0.0f;
    }
    sStat[tid] = 0.0f;
    sStat[256 + tid] = 0.0f;
    // zero both fragment buffers (pad rows 66..79 stay zero forever)
    for (int i = tid; i < 2560; i += 256) sA2[i] = 0;

    // ---- per-thread fragment jobs (verified layout, R10+) ----
    const int pair = lane & 15;
    const int half = lane >> 4;
    int rr_[5];
    uint32_t soff_[5];
    bool act_[5];
    #pragma unroll
    for (int j = 0; j < 5; j++) {
        int r = warp + 16 * j + 8 * half;
        act_[j] = (r < TROWS);
        int rc = act_[j] ? r : 0;
        rr_[j] = rc;
        int tl   = rc >> 4;
        int s    = pair >> 3;
        int lp   = (rc & 7) * 4 + (pair & 3);
        int comp = ((rc >> 3) & 1) + (((pair >> 2) & 1) << 1);
        soff_[j] = ((tl * 2 + s) * 32 + lp) * 4 + comp;
    }

    // ---- prefetch input chunk 0 (coalesced: 2x128B per warp per job) ----
    float2 pin[5];
    #pragma unroll
    for (int j = 0; j < 5; j++)
        if (act_[j])
            pin[j] = *(const float2*)&src[(size_t)rr_[j] * HDIM + pair * 2];

    float acc[5][4][4];
    #pragma unroll
    for (int i = 0; i < 5; i++)
        #pragma unroll
        for (int nt = 0; nt < 4; nt++)
            #pragma unroll
            for (int j = 0; j < 4; j++) acc[i][nt][j] = 0.0f;

    __syncthreads();   // init (sScale/sNW/sA2 zeros) visible

    for (int c = 0; c < 8; c++) {
        // ---- B[c] fragments (L2-resident; latency hides under pack) ----
        uint2 bfr[2][4];
        #pragma unroll
        for (int s = 0; s < 2; s++)
            #pragma unroll
            for (int nt = 0; nt < 4; nt++)
                bfr[s][nt] = __ldg(&wbase[((c * 32 + warp * 4 + nt) * 2 + s) * 32 + lane]);

        // ---- pack[c]: BN+ReLU (or nan_to_num) -> fp16 fragments ----
        {
            uint32_t* sAc = sA2 + (c & 1) * 1280;
            float2 sc2 = *(const float2*)&sScale[c * 32 + pair * 2];
            float2 sh2 = *(const float2*)&sShift[c * 32 + pair * 2];
            #pragma unroll
            for (int j = 0; j < 5; j++) {
                if (act_[j]) {
                    float fx, fy;
                    if (mode == 0) {
                        fx = fixv(pin[j].x); fy = fixv(pin[j].y);
                    } else {
                        fx = fmaxf(fmaf(pin[j].x, sc2.x, sh2.x), 0.0f);
                        fy = fmaxf(fmaf(pin[j].y, sc2.y, sh2.y), 0.0f);
                    }
                    sAc[soff_[j]] = pack_h2(fx, fy);
                }
            }
        }

        // ---- prefetch input chunk c+1 (latency hides under bar + MMA) ----
        if (c + 1 < 8) {
            #pragma unroll
            for (int j = 0; j < 5; j++)
                if (act_[j])
                    pin[j] = *(const float2*)&src[(size_t)rr_[j] * HDIM + (c + 1) * 32 + pair * 2];
        }

        __syncthreads();   // fragments[c] visible; also fences sA2 reuse

        // ---- MMA[c] ----
        {
            const uint32_t* sAc = sA2 + (c & 1) * 1280;
            #pragma unroll
            for (int s = 0; s < 2; s++) {
                #pragma unroll
                for (int tl = 0; tl < 5; tl++) {
                    uint4 av = *(const uint4*)&sAc[((tl * 2 + s) * 32 + lane) * 4];
                    const uint32_t* af = (const uint32_t*)&av;
                    #pragma unroll
                    for (int nt = 0; nt < 4; nt++)
                        mma_f16(acc[tl][nt], af, (const uint32_t*)&bfr[s][nt]);
                }
            }
        }
    }

    // ---- epilogue: U = A_hat * Z + b per warp via private slab ----
    float* slab = sSlab + warp * 1280;   // [80][16]
    const int cl = lane >> 1, rh = lane & 1;

    #pragma unroll
    for (int h = 0; h < 2; h++) {
        // write acc column-half h into slab
        #pragma unroll
        for (int tl = 0; tl < 5; tl++) {
            #pragma unroll
            for (int q = 0; q < 2; q++) {
                int nt = 2 * h + q;
                int r0 = 16 * tl + (lane >> 2);
                int c16 = q * 8 + 2 * (lane & 3);
                *(float2*)&slab[r0 * 16 + c16] =
                    make_float2(acc[tl][nt][0], acc[tl][nt][1]);
                *(float2*)&slab[(r0 + 8) * 16 + c16] =
                    make_float2(acc[tl][nt][2], acc[tl][nt][3]);
            }
        }
        __syncwarp();

        const int col = warp * 32 + h * 16 + cl;
        const float bv = bias[col];
        float s1 = 0.0f, s2 = 0.0f;
        #pragma unroll 4
        for (int i = 0; i < 33; i++) {
            int r = 2 * i + rh;
            int gb = (r >= NUM_JOINTS) ? NUM_JOINTS : 0;
            int n  = r - gb;
            float sum = 0.0f;
            int e1 = ADJ_OFF[n + 1];
            for (int e = ADJ_OFF[n]; e < e1; e++)
                sum = fmaf(sNW[e], slab[(gb + ADJ_NB[e]) * 16 + cl], sum);
            float z = sum + bv;
            out[(size_t)(rowBase + r) * HDIM + col] = z;
            s1 += z;
            s2 = fmaf(z, z, s2);
        }
        if (stats_out != nullptr) {
            atomicAdd(&sStat[col], s1);
            atomicAdd(&sStat[256 + col], s2);
        }
        __syncwarp();   // slab dead before h=1 overwrite
    }

    if (stats_out != nullptr) {
        __syncthreads();
        atomicAdd(&stats_out[tid], sStat[tid]);
        atomicAdd(&stats_out[256 + tid], sStat[256 + tid]);
    }
}

// ---------------------------------------------------------------------------
__global__ void __launch_bounds__(256)
pool_kernel(const float* __restrict__ h, const float* __restrict__ wc,
            const float* __restrict__ bc, float* __restrict__ out)
{
    const int g = blockIdx.x;
    const int tid = threadIdx.x;
    const int lane = tid & 31, warp = tid >> 5;
    const size_t base = (size_t)g * NUM_JOINTS * HDIM;

    float s = 0.0f;
    #pragma unroll
    for (int n = 0; n < NUM_JOINTS; n++) s += h[base + n * HDIM + tid];
    s *= (1.0f / 33.0f);

    float4 wv = *(const float4*)(wc + tid * 4);
    float p0 = s * wv.x, p1 = s * wv.y, p2 = s * wv.z, p3 = s * wv.w;
    #pragma unroll
    for (int off = 16; off > 0; off >>= 1) {
        p0 += __shfl_down_sync(0xFFFFFFFF, p0, off);
        p1 += __shfl_down_sync(0xFFFFFFFF, p1, off);
        p2 += __shfl_down_sync(0xFFFFFFFF, p2, off);
        p3 += __shfl_down_sync(0xFFFFFFFF, p3, off);
    }
    __shared__ float4 part[8];
    if (lane == 0) part[warp] = make_float4(p0, p1, p2, p3);
    __syncthreads();
    if (tid == 0) {
        float4 o = make_float4(bc[0], bc[1], bc[2], bc[3]);
        #pragma unroll
        for (int w = 0; w < 8; w++) {
            o.x += part[w].x; o.y += part[w].y; o.z += part[w].z; o.w += part[w].w;
        }
        *(float4*)(out + g * 4) = o;
    }
}

// ---------------------------------------------------------------------------
extern "C" void kernel_launch(void* const* d_in, const int* in_sizes, int n_in,
                              void* d_out, int out_size)
{
    const float* x   = (const float*)d_in[0];
    const float* w0  = (const float*)d_in[1];
    const float* b0  = (const float*)d_in[2];
    const float* g0  = (const float*)d_in[3];
    const float* be0 = (const float*)d_in[4];
    const float* w1  = (const float*)d_in[5];
    const float* b1  = (const float*)d_in[6];
    const float* g1  = (const float*)d_in[7];
    const float* be1 = (const float*)d_in[8];
    const float* w2  = (const float*)d_in[9];
    const float* b2  = (const float*)d_in[10];
    const float* g2  = (const float*)d_in[11];
    const float* be2 = (const float*)d_in[12];
    const float* wh  = (const float*)d_in[13];
    const float* bh  = (const float*)d_in[14];
    const float* wc  = (const float*)d_in[15];
    const float* bc  = (const float*)d_in[16];

    float *bufA, *bufB, *stats;
    cudaGetSymbolAddress((void**)&bufA, g_bufA);
    cudaGetSymbolAddress((void**)&bufB, g_bufB);
    cudaGetSymbolAddress((void**)&stats, g_stats);

    cudaFuncSetAttribute(fused_layer, cudaFuncAttributeMaxDynamicSharedMemorySize,
                         SMEM_BYTES);

    pack_w<<<256, 256>>>(w0, w1, w2, wh);
    zero_stats_kernel<<<6, 256>>>(stats);

    fused_layer<<<NTILES, 256, SMEM_BYTES>>>(x,    0, b0, bufB, nullptr, nullptr, nullptr, stats, 0);
    fused_layer<<<NTILES, 256, SMEM_BYTES>>>(bufB, 1, b1, bufA, stats,        g0, be0, stats + 512, 1);
    fused_layer<<<NTILES, 256, SMEM_BYTES>>>(bufA, 2, b2, bufB, stats + 512,  g1, be1, stats + 1024, 1);
    fused_layer<<<NTILES, 256, SMEM_BYTES>>>(bufB, 3, bh, bufA, stats + 1024, g2, be2, nullptr, 1);
    pool_kernel<<<BATCH, 256>>>(bufA, wc, bc, (float*)d_out);
}

// round 17
// speedup vs baseline: 1.2731x; 1.0718x over previous
#include <cuda_runtime.h>
#include <cuda_bf16.h>
#include <cuda_fp16.h>
#include <math.h>
#include <float.h>
#include <stdint.h>

// ---------------------------------------------------------------------------
// MultiLabelGCN on GB300 — R17: N split to 128/CTA -> 3 CTAs/SM (24 warps).
//   Z = BN_ReLU(H) @ W half-N per CTA (fp16 m16n8k16, B in registers),
//   U = A_hat*Z + b in per-warp slab epilogue. Grid (2, 2048).
// ---------------------------------------------------------------------------

#define NUM_JOINTS 33
#define BATCH      4096
#define NN_ROWS    (BATCH * NUM_JOINTS)   // 135168
#define HDIM       256
#define NN_INV     (1.0f / 135168.0f)

#define NTILES (NN_ROWS / 66)       // 2048 row-tiles
#define TROWS  66

// smem layout (bytes)
#define OFF_A2     0                        // u32 [2][1280]       10240
#define OFF_SLAB   10240                    // float [8][80*16]    40960
#define OFF_SCALE  51200                    // float [256]          1024
#define OFF_SHIFT  52224                    // float [256]          1024
#define OFF_STAT   53248                    // float [256]          1024
#define OFF_NW     54272                    // float [103] + pad     512
#define SMEM_BYTES 54784

__constant__ int ADJ_OFF[34] = {
    0,3,6,9,12,15,18,21,23,25,27,29,33,37,40,43,48,53,56,59,62,65,
    67,69,73,77,80,83,87,91,94,97,100,103};
__constant__ int ADJ_NB[103] = {
    1,4,0,  0,2,1,  1,3,2,  2,7,3,  0,5,4,  4,6,5,  5,8,6,  3,7,  6,8,
    10,9,  9,10,  12,13,23,11,  11,14,24,12,  11,15,13,  12,16,14,
    13,17,19,21,15,  14,18,20,22,16,  15,19,17,  16,20,18,  15,17,19,
    16,18,20,  15,21,  16,22,  11,24,25,23,  12,23,26,24,  23,27,25,
    24,28,26,  25,29,31,27,  26,30,32,28,  27,31,29,  28,32,30,
    29,27,31,  30,28,32};
__constant__ float DEGF[33] = {
    3,3,3,3,3,3,3,2,2,2,2,4,4,3,3,5,5,3,3,3,3,2,2,4,4,3,3,4,4,3,3,3,3};

// scratch — fp32 activations
__device__ float g_bufA[(size_t)NN_ROWS * HDIM];
__device__ float g_bufB[(size_t)NN_ROWS * HDIM];
__device__ float g_stats[3 * 512];
__device__ uint2 g_wpackH[4 * 8 * 32 * 2 * 32];  // [mat][chunk][ntile][s][lane]

// ---------------------------------------------------------------------------
__device__ __forceinline__ uint32_t pack_h2(float a, float b) {
    __half2 h = __float22half2_rn(make_float2(a, b));
    return *(uint32_t*)&h;
}
__device__ __forceinline__ void mma_f16(float* d, const uint32_t* a, const uint32_t* b) {
    asm volatile(
        "mma.sync.aligned.m16n8k16.row.col.f32.f16.f16.f32 "
        "{%0,%1,%2,%3}, {%4,%5,%6,%7}, {%8,%9}, {%0,%1,%2,%3};\n"
        : "+f"(d[0]), "+f"(d[1]), "+f"(d[2]), "+f"(d[3])
        : "r"(a[0]), "r"(a[1]), "r"(a[2]), "r"(a[3]), "r"(b[0]), "r"(b[1]));
}
__device__ __forceinline__ float fixv(float f) {
    if (isnan(f)) return 0.0f;
    return fminf(fmaxf(f, -60000.0f), 60000.0f);
}

// ---------------------------------------------------------------------------
// pack weights -> fp16 B fragments (layout verified R10-R16)
// ---------------------------------------------------------------------------
__global__ void pack_w(const float* __restrict__ w0, const float* __restrict__ w1,
                       const float* __restrict__ w2, const float* __restrict__ wh)
{
    int idx = blockIdx.x * blockDim.x + threadIdx.x;   // 0..65535
    int lane  = idx & 31;
    int s     = (idx >> 5) & 1;
    int ntile = (idx >> 6) & 31;
    int c     = (idx >> 11) & 7;
    int m     = idx >> 14;
    const float* W = (m == 0) ? w0 : (m == 1) ? w1 : (m == 2) ? w2 : wh;
    int k0 = c * 32 + s * 16;
    int n  = ntile * 8 + (lane >> 2);
    int t  = lane & 3;
    uint2 v;
    v.x = pack_h2(W[(size_t)(k0 + 2*t)     * HDIM + n], W[(size_t)(k0 + 2*t + 1) * HDIM + n]);
    v.y = pack_h2(W[(size_t)(k0 + 2*t + 8) * HDIM + n], W[(size_t)(k0 + 2*t + 9) * HDIM + n]);
    g_wpackH[idx] = v;
}

__global__ void zero_stats_kernel(float* stats) {
    int i = blockIdx.x * blockDim.x + threadIdx.x;
    if (i < 3 * 512) stats[i] = 0.0f;
}

// ---------------------------------------------------------------------------
// fused layer. grid = (2, NTILES), block = 256, 3 CTAs/SM.
// blockIdx.x = N-half, blockIdx.y = row tile.
// ---------------------------------------------------------------------------
__global__ void __launch_bounds__(256, 3)
fused_layer(const float* __restrict__ in, int wsel, const float* __restrict__ bias,
            float* __restrict__ out, const float* __restrict__ stats_in,
            const float* __restrict__ gam, const float* __restrict__ bet,
            float* __restrict__ stats_out, int mode)
{
    extern __shared__ char smem[];
    uint32_t* sA2   = (uint32_t*)(smem + OFF_A2);  // [2][1280]
    float*    sSlab = (float*)(smem + OFF_SLAB);   // [8][80*16]
    float*    sScale= (float*)(smem + OFF_SCALE);
    float*    sShift= (float*)(smem + OFF_SHIFT);
    float*    sStat = (float*)(smem + OFF_STAT);   // [256]: 128 sum, 128 sumsq
    float*    sNW   = (float*)(smem + OFF_NW);

    const int tid = threadIdx.x, lane = tid & 31, warp = tid >> 5;   // 8 warps
    const int nh = blockIdx.x;            // N half (0/1)
    const int p  = blockIdx.y;
    const int rowBase = p * TROWS;
    const int colBase = nh * 128;
    const float* src = in + (size_t)rowBase * HDIM;
    const uint2* wbase = g_wpackH + (size_t)wsel * (8 * 32 * 2 * 32);

    // ---- init ----
    if (tid < NUM_JOINTS) {
        float dn = rsqrtf(DEGF[tid]);
        for (int e = ADJ_OFF[tid]; e < ADJ_OFF[tid + 1]; e++)
            sNW[e] = dn * rsqrtf(DEGF[ADJ_NB[e]]);
    }
    if (mode == 1) {
        float mu  = stats_in[tid] * NN_INV;
        float ex2 = stats_in[256 + tid] * NN_INV;
        float inv = rsqrtf(ex2 - mu * mu + 1e-5f);
        float sc  = inv * gam[tid];
        sScale[tid] = sc;
        sShift[tid] = bet[tid] - mu * sc;
    } else {
        sScale[tid] = 1.0f;
        sShift[tid] = 0.0f;
    }
    sStat[tid] = 0.0f;
    // zero both fragment buffers (pad rows 66..79 stay zero forever)
    for (int i = tid; i < 2560; i += 256) sA2[i] = 0;

    // ---- per-thread fragment jobs (verified layout) ----
    const int pair = lane & 15;
    const int half = lane >> 4;
    int rr_[5];
    uint32_t soff_[5];
    bool act_[5];
    #pragma unroll
    for (int j = 0; j < 5; j++) {
        int r = warp + 16 * j + 8 * half;
        act_[j] = (r < TROWS);
        int rc = act_[j] ? r : 0;
        rr_[j] = rc;
        int tl   = rc >> 4;
        int s    = pair >> 3;
        int lp   = (rc & 7) * 4 + (pair & 3);
        int comp = ((rc >> 3) & 1) + (((pair >> 2) & 1) << 1);
        soff_[j] = ((tl * 2 + s) * 32 + lp) * 4 + comp;
    }

    // ---- prefetch input chunk 0 ----
    float2 pin[5];
    #pragma unroll
    for (int j = 0; j < 5; j++)
        if (act_[j])
            pin[j] = *(const float2*)&src[(size_t)rr_[j] * HDIM + pair * 2];

    float acc[5][2][4];
    #pragma unroll
    for (int i = 0; i < 5; i++)
        #pragma unroll
        for (int nt = 0; nt < 2; nt++)
            #pragma unroll
            for (int j = 0; j < 4; j++) acc[i][nt][j] = 0.0f;

    __syncthreads();   // init visible

    for (int c = 0; c < 8; c++) {
        // ---- B[c] fragments: this CTA's N-half (2 ntiles/warp) ----
        uint2 bfr[2][2];
        #pragma unroll
        for (int s = 0; s < 2; s++)
            #pragma unroll
            for (int nt = 0; nt < 2; nt++)
                bfr[s][nt] = __ldg(&wbase[((c * 32 + nh * 16 + warp * 2 + nt) * 2 + s) * 32 + lane]);

        // ---- pack[c]: BN+ReLU / nan_to_num -> fp16 fragments ----
        {
            uint32_t* sAc = sA2 + (c & 1) * 1280;
            float2 sc2 = *(const float2*)&sScale[c * 32 + pair * 2];
            float2 sh2 = *(const float2*)&sShift[c * 32 + pair * 2];
            #pragma unroll
            for (int j = 0; j < 5; j++) {
                if (act_[j]) {
                    float fx, fy;
                    if (mode == 0) {
                        fx = fixv(pin[j].x); fy = fixv(pin[j].y);
                    } else {
                        fx = fmaxf(fmaf(pin[j].x, sc2.x, sh2.x), 0.0f);
                        fy = fmaxf(fmaf(pin[j].y, sc2.y, sh2.y), 0.0f);
                    }
                    sAc[soff_[j]] = pack_h2(fx, fy);
                }
            }
        }

        // ---- prefetch input chunk c+1 ----
        if (c + 1 < 8) {
            #pragma unroll
            for (int j = 0; j < 5; j++)
                if (act_[j])
                    pin[j] = *(const float2*)&src[(size_t)rr_[j] * HDIM + (c + 1) * 32 + pair * 2];
        }

        __syncthreads();   // fragments[c] visible; fences sA2 reuse

        // ---- MMA[c] ----
        {
            const uint32_t* sAc = sA2 + (c & 1) * 1280;
            #pragma unroll
            for (int s = 0; s < 2; s++) {
                #pragma unroll
                for (int tl = 0; tl < 5; tl++) {
                    uint4 av = *(const uint4*)&sAc[((tl * 2 + s) * 32 + lane) * 4];
                    const uint32_t* af = (const uint32_t*)&av;
                    #pragma unroll
                    for (int nt = 0; nt < 2; nt++)
                        mma_f16(acc[tl][nt], af, (const uint32_t*)&bfr[s][nt]);
                }
            }
        }
    }

    // ---- epilogue: U = A_hat * Z + b, per-warp slab (16 cols/warp) ----
    float* slab = sSlab + warp * 1280;   // [80][16]
    const int cl = lane >> 1, rh = lane & 1;

    #pragma unroll
    for (int tl = 0; tl < 5; tl++) {
        #pragma unroll
        for (int nt = 0; nt < 2; nt++) {
            int r0 = 16 * tl + (lane >> 2);
            int c16 = nt * 8 + 2 * (lane & 3);
            *(float2*)&slab[r0 * 16 + c16] =
                make_float2(acc[tl][nt][0], acc[tl][nt][1]);
            *(float2*)&slab[(r0 + 8) * 16 + c16] =
                make_float2(acc[tl][nt][2], acc[tl][nt][3]);
        }
    }
    __syncwarp();

    {
        const int col = colBase + warp * 16 + cl;
        const float bv = bias[col];
        float s1 = 0.0f, s2 = 0.0f;
        #pragma unroll 4
        for (int i = 0; i < 33; i++) {
            int r = 2 * i + rh;
            int gb = (r >= NUM_JOINTS) ? NUM_JOINTS : 0;
            int n  = r - gb;
            float sum = 0.0f;
            int e1 = ADJ_OFF[n + 1];
            for (int e = ADJ_OFF[n]; e < e1; e++)
                sum = fmaf(sNW[e], slab[(gb + ADJ_NB[e]) * 16 + cl], sum);
            float z = sum + bv;
            out[(size_t)(rowBase + r) * HDIM + col] = z;
            s1 += z;
            s2 = fmaf(z, z, s2);
        }
        if (stats_out != nullptr) {
            int lc = warp * 16 + cl;           // 0..127
            atomicAdd(&sStat[lc], s1);
            atomicAdd(&sStat[128 + lc], s2);
        }
    }

    if (stats_out != nullptr) {
        __syncthreads();
        if (tid < 128) {
            atomicAdd(&stats_out[colBase + tid], sStat[tid]);
            atomicAdd(&stats_out[256 + colBase + tid], sStat[128 + tid]);
        }
    }
}

// ---------------------------------------------------------------------------
__global__ void __launch_bounds__(256)
pool_kernel(const float* __restrict__ h, const float* __restrict__ wc,
            const float* __restrict__ bc, float* __restrict__ out)
{
    const int g = blockIdx.x;
    const int tid = threadIdx.x;
    const int lane = tid & 31, warp = tid >> 5;
    const size_t base = (size_t)g * NUM_JOINTS * HDIM;

    float s = 0.0f;
    #pragma unroll
    for (int n = 0; n < NUM_JOINTS; n++) s += h[base + n * HDIM + tid];
    s *= (1.0f / 33.0f);

    float4 wv = *(const float4*)(wc + tid * 4);
    float p0 = s * wv.x, p1 = s * wv.y, p2 = s * wv.z, p3 = s * wv.w;
    #pragma unroll
    for (int off = 16; off > 0; off >>= 1) {
        p0 += __shfl_down_sync(0xFFFFFFFF, p0, off);
        p1 += __shfl_down_sync(0xFFFFFFFF, p1, off);
        p2 += __shfl_down_sync(0xFFFFFFFF, p2, off);
        p3 += __shfl_down_sync(0xFFFFFFFF, p3, off);
    }
    __shared__ float4 part[8];
    if (lane == 0) part[warp] = make_float4(p0, p1, p2, p3);
    __syncthreads();
    if (tid == 0) {
        float4 o = make_float4(bc[0], bc[1], bc[2], bc[3]);
        #pragma unroll
        for (int w = 0; w < 8; w++) {
            o.x += part[w].x; o.y += part[w].y; o.z += part[w].z; o.w += part[w].w;
        }
        *(float4*)(out + g * 4) = o;
    }
}

// ---------------------------------------------------------------------------
extern "C" void kernel_launch(void* const* d_in, const int* in_sizes, int n_in,
                              void* d_out, int out_size)
{
    const float* x   = (const float*)d_in[0];
    const float* w0  = (const float*)d_in[1];
    const float* b0  = (const float*)d_in[2];
    const float* g0  = (const float*)d_in[3];
    const float* be0 = (const float*)d_in[4];
    const float* w1  = (const float*)d_in[5];
    const float* b1  = (const float*)d_in[6];
    const float* g1  = (const float*)d_in[7];
    const float* be1 = (const float*)d_in[8];
    const float* w2  = (const float*)d_in[9];
    const float* b2  = (const float*)d_in[10];
    const float* g2  = (const float*)d_in[11];
    const float* be2 = (const float*)d_in[12];
    const float* wh  = (const float*)d_in[13];
    const float* bh  = (const float*)d_in[14];
    const float* wc  = (const float*)d_in[15];
    const float* bc  = (const float*)d_in[16];

    float *bufA, *bufB, *stats;
    cudaGetSymbolAddress((void**)&bufA, g_bufA);
    cudaGetSymbolAddress((void**)&bufB, g_bufB);
    cudaGetSymbolAddress((void**)&stats, g_stats);

    cudaFuncSetAttribute(fused_layer, cudaFuncAttributeMaxDynamicSharedMemorySize,
                         SMEM_BYTES);

    pack_w<<<256, 256>>>(w0, w1, w2, wh);
    zero_stats_kernel<<<6, 256>>>(stats);

    dim3 gg(2, NTILES);
    fused_layer<<<gg, 256, SMEM_BYTES>>>(x,    0, b0, bufB, nullptr, nullptr, nullptr, stats, 0);
    fused_layer<<<gg, 256, SMEM_BYTES>>>(bufB, 1, b1, bufA, stats,        g0, be0, stats + 512, 1);
    fused_layer<<<gg, 256, SMEM_BYTES>>>(bufA, 2, b2, bufB, stats + 512,  g1, be1, stats + 1024, 1);
    fused_layer<<<gg, 256, SMEM_BYTES>>>(bufB, 3, bh, bufA, stats + 1024, g2, be2, nullptr, 1);
    pool_kernel<<<BATCH, 256>>>(bufA, wc, bc, (float*)d_out);
}